// round 9
// baseline (speedup 1.0000x reference)
#include <cuda_runtime.h>
#include <cstdint>

#define B_  8
#define C_  64
#define H_  64
#define W_  64
#define NN  9
#define M_  18
#define HP  66
#define KTOT 576

typedef unsigned long long ull;

__device__ float g_offset[B_ * M_ * H_ * W_];
__device__ float g_Wp[KTOT * C_];   // g_Wp[(ci*9+n)*64 + co] = Wc[co][ci*9+n]

// ---------------- helpers ----------------
__device__ __forceinline__ void ffma2(ull& d, ull a, ull b) {
    asm("fma.rn.f32x2 %0, %1, %2, %0;" : "+l"(d) : "l"(a), "l"(b));
}
__device__ __forceinline__ float2 unpack2(ull v) {
    float2 r; asm("mov.b64 {%0, %1}, %2;" : "=f"(r.x), "=f"(r.y) : "l"(v)); return r;
}
__device__ __forceinline__ ull dup2(float v) {
    ull r; asm("mov.b64 %0, {%1, %1};" : "=l"(r) : "f"(v)); return r;
}
__device__ __forceinline__ ull pack2(float lo, float hi) {
    ull r; asm("mov.b64 %0, {%1, %2};" : "=l"(r) : "f"(lo), "f"(hi)); return r;
}

// ---------------------------------------------------------------------------
// K1: offset conv (FFMA2 over m-pairs), 16x8 pixel tiles, 128 threads.
// z==8 slice preps g_Wp.
// ---------------------------------------------------------------------------
#define K1_SMEM ((64*180 + 64*9*10*2) * 4)   // 92160 B

__global__ __launch_bounds__(128, 2)
void k1_offset_conv(const float* __restrict__ x,
                    const float* __restrict__ Woff,
                    const float* __restrict__ boff,
                    const float* __restrict__ Wc) {
    if (blockIdx.z == 8) {
        int base = (blockIdx.y * 4 + blockIdx.x) * 128 + threadIdx.x;
        for (int i = base; i < KTOT * C_; i += 32 * 128)
            g_Wp[i] = Wc[(i & 63) * KTOT + (i >> 6)];
        return;
    }

    extern __shared__ float smem[];
    float*  xs  = smem;                        // [ci][10][18]
    float2* ws2 = (float2*)(smem + 64 * 180);  // [ci][9][10]

    const int tid = threadIdx.x;
    const int b   = blockIdx.z;
    const int th0 = blockIdx.y * 8;
    const int tw0 = blockIdx.x * 16;

    const float* xb = x + (size_t)b * C_ * H_ * W_;
    for (int idx = tid; idx < 64 * 180; idx += 128) {
        int ci = idx / 180;
        int rem = idx % 180;
        int r = rem / 18, c = rem % 18;
        int gh = th0 + r - 1, gw = tw0 + c - 1;
        float v = 0.f;
        if ((unsigned)gh < H_ && (unsigned)gw < W_)
            v = xb[(ci * H_ + gh) * W_ + gw];
        xs[idx] = v;
    }
    for (int idx = tid; idx < 64 * 81; idx += 128) {
        int ci = idx / 81;
        int rem = idx % 81;
        int j = rem / 9, t = rem % 9;
        ws2[(ci * 9 + j) * 10 + t] =
            make_float2(Woff[(2 * j)     * 576 + ci * 9 + t],
                        Woff[(2 * j + 1) * 576 + ci * 9 + t]);
    }
    __syncthreads();

    const int lh = tid >> 4, lw = tid & 15;
    ull acc[9];
#pragma unroll
    for (int j = 0; j < 9; j++) acc[j] = pack2(boff[2 * j], boff[2 * j + 1]);

    for (int ci = 0; ci < 64; ci++) {
        ull xd[9];
        const float* xc = xs + ci * 180 + lh * 18 + lw;
#pragma unroll
        for (int u = 0; u < 3; u++)
#pragma unroll
            for (int v = 0; v < 3; v++)
                xd[u * 3 + v] = dup2(xc[u * 18 + v]);
#pragma unroll
        for (int j = 0; j < 9; j++) {
            const ulonglong2* wp = (const ulonglong2*)(ws2 + (ci * 9 + j) * 10);
            ulonglong2 wA = wp[0];
            ulonglong2 wB = wp[1];
            ulonglong2 wC = wp[2];
            ulonglong2 wD = wp[3];
            ull        wE = *(const ull*)(ws2 + (ci * 9 + j) * 10 + 8);
            ffma2(acc[j], wA.x, xd[0]); ffma2(acc[j], wA.y, xd[1]);
            ffma2(acc[j], wB.x, xd[2]); ffma2(acc[j], wB.y, xd[3]);
            ffma2(acc[j], wC.x, xd[4]); ffma2(acc[j], wC.y, xd[5]);
            ffma2(acc[j], wD.x, xd[6]); ffma2(acc[j], wD.y, xd[7]);
            ffma2(acc[j], wE,   xd[8]);
        }
    }

    const int h = th0 + lh, w = tw0 + lw;
#pragma unroll
    for (int j = 0; j < 9; j++) {
        float2 v = unpack2(acc[j]);
        g_offset[((b * M_ + 2 * j)     * H_ + h) * W_ + w] = v.x;
        g_offset[((b * M_ + 2 * j + 1) * H_ + h) * W_ + w] = v.y;
    }
}

// ---------------------------------------------------------------------------
// K2: fused bilinear sampling + GEMM with smem window staging.
// Block = (b, 1 row) = 64 px, 128 threads. Chunk = 8 ci x 9 n = 72 k-rows.
// Per chunk: stage 15-row windows of 8 channels (coalesced LDG.128), sample
// via LDS, GEMM 8px x 4co FFMA2. Fallback to LDG gather if any valid corner
// falls outside the window (block-uniform, ~never).
// ---------------------------------------------------------------------------
#define NSAMP 576
#define WINR  15
#define SM_Q    0                                // ushort4[576]   = 4608
#define SM_G    (SM_Q + NSAMP * 8)               // float4[576]    = 9216
#define SM_FLAG (SM_G + NSAMP * 16)              // int (+pad)     = 16
#define SM_WS   (SM_FLAG + 16)                   // [8][15][64]    = 30720
#define SM_XO   (SM_WS + 8 * WINR * 64 * 4)      // [72][64]       = 18432
#define SM_W    (SM_XO + 72 * 64 * 4)            // [72][64]       = 18432
#define K2_SMEM (SM_W + 72 * 64 * 4)             // 81424

__global__ __launch_bounds__(128, 2)
void k2_sample_gemm(const float* __restrict__ x, float* __restrict__ out) {
    extern __shared__ char smc[];
    ushort4* s_q  = (ushort4*)(smc + SM_Q);
    float4*  s_g  = (float4*)(smc + SM_G);
    int*     s_fl = (int*)(smc + SM_FLAG);
    float*   ws_s = (float*)(smc + SM_WS);
    float*   xo_s = (float*)(smc + SM_XO);
    float*   w_s  = (float*)(smc + SM_W);

    const int tid = threadIdx.x;
    const int h   = blockIdx.x;
    const int b   = blockIdx.y;

    if (tid == 0) *s_fl = 0;
    __syncthreads();

    // ---- Phase A: absolute element offsets + pre-zeroed weights + OOW flag -
    for (int t = tid; t < NSAMP; t += 128) {
        int n  = t >> 6;
        int px = t & 63;
        float offx = g_offset[((b * M_ + n)     * H_ + h) * W_ + px];
        float offy = g_offset[((b * M_ + 9 + n) * H_ + h) * W_ + px];
        float pX = (float)(h + 1)  + (float)(n / 3 - 1) + offx;
        float pY = (float)(px + 1) + (float)(n % 3 - 1) + offy;
        float fx = floorf(pX), fy = floorf(pY);
        int x0 = min(max((int)fx,     0), HP - 1);
        int x1 = min(max((int)fx + 1, 0), HP - 1);
        int y0 = min(max((int)fy,     0), HP - 1);
        int y1 = min(max((int)fy + 1, 0), HP - 1);
        float pxc = fminf(fmaxf(pX, 0.f), (float)(HP - 1));
        float pyc = fminf(fmaxf(pY, 0.f), (float)(HP - 1));
        float gx0 = 1.f + ((float)x0 - pxc);
        float gx1 = 1.f - ((float)x1 - pxc);
        float gy0 = 1.f + ((float)y0 - pyc);
        float gy1 = 1.f - ((float)y1 - pyc);
        int ix0 = x0 - 1, iy0 = y0 - 1, ix1 = x1 - 1, iy1 = y1 - 1;
        bool vx0 = (unsigned)ix0 < H_, vy0 = (unsigned)iy0 < W_;
        bool vx1 = (unsigned)ix1 < H_, vy1 = (unsigned)iy1 < W_;
        int cx0 = min(max(ix0, 0), H_ - 1);
        int cx1 = min(max(ix1, 0), H_ - 1);
        int cy0 = min(max(iy0, 0), W_ - 1);
        int cy1 = min(max(iy1, 0), W_ - 1);
        s_q[t] = make_ushort4((unsigned short)((cx0 << 6) + cy0),
                              (unsigned short)((cx1 << 6) + cy1),
                              (unsigned short)((cx0 << 6) + cy1),
                              (unsigned short)((cx1 << 6) + cy0));
        s_g[t] = make_float4(vx0 && vy0 ? gx0 * gy0 : 0.f,
                             vx1 && vy1 ? gx1 * gy1 : 0.f,
                             vx0 && vy1 ? gx0 * gy1 : 0.f,
                             vx1 && vy0 ? gx1 * gy0 : 0.f);
        bool oow = (vx0 && (ix0 < h - 7 || ix0 > h + 7))
                || (vx1 && (ix1 < h - 7 || ix1 > h + 7));
        if (oow) atomicOr(s_fl, 1);
    }
    __syncthreads();
    const int flag = *s_fl;

    const int px   = tid & 63;        // gather pixel
    const int half = tid >> 6;        // gather ci half (4 ci each)
    const int ciw  = tid >> 4;        // window: ci 0..7
    const int fq   = tid & 15;        // window: float4 idx in row
    const int pg   = tid >> 4;        // GEMM: 8 groups x 8 px
    const int cg   = tid & 15;        // GEMM: 16 groups x 4 co
    const float* xbase = x + (size_t)b * C_ * H_ * W_;
    const int rbase = (h - 7) * 64;

    ull acc[4][4];
#pragma unroll
    for (int i = 0; i < 4; i++)
#pragma unroll
        for (int j = 0; j < 4; j++) acc[i][j] = 0ull;

    for (int c = 0; c < 8; c++) {
        const int cg0 = c * 8;
        __syncthreads();   // prev gather done with ws, prev GEMM done with xo/w

        // window staging: 8 ci x 15 rows x 64 cols, coalesced
        {
            const float* xsrc = xbase + ((cg0 + ciw) << 12);
            float4* wdst = (float4*)(ws_s + ciw * (WINR * 64)) + fq;
#pragma unroll
            for (int wr = 0; wr < WINR; wr++) {
                int sr = min(max(h - 7 + wr, 0), H_ - 1);
                wdst[wr * 16] = __ldg((const float4*)(xsrc + (sr << 6)) + fq);
            }
        }
        // B chunk
        {
            const float4* src = (const float4*)(g_Wp + c * (72 * 64));
            float4* dst = (float4*)w_s;
#pragma unroll
            for (int j = 0; j < 9; j++)
                dst[j * 128 + tid] = src[j * 128 + tid];
        }
        __syncthreads();

        // gather: 36 samples/thread
        if (!flag) {
#pragma unroll
            for (int n = 0; n < NN; n++) {
                ushort4 q = s_q[n * 64 + px];
                float4  g = s_g[n * 64 + px];
                int r0 = min(max((int)q.x - rbase, 0), WINR * 64 - 1);
                int r1 = min(max((int)q.y - rbase, 0), WINR * 64 - 1);
                int r2 = min(max((int)q.z - rbase, 0), WINR * 64 - 1);
                int r3 = min(max((int)q.w - rbase, 0), WINR * 64 - 1);
#pragma unroll
                for (int cil = 0; cil < 4; cil++) {
                    int cl = half * 4 + cil;
                    const float* w = ws_s + cl * (WINR * 64);
                    float v = g.x * w[r0] + g.y * w[r1]
                            + g.z * w[r2] + g.w * w[r3];
                    xo_s[(cl * 9 + n) * 64 + px] = v;
                }
            }
        } else {
#pragma unroll
            for (int n = 0; n < NN; n++) {
                ushort4 q = s_q[n * 64 + px];
                float4  g = s_g[n * 64 + px];
#pragma unroll
                for (int cil = 0; cil < 4; cil++) {
                    int cl = half * 4 + cil;
                    const float* xc = xbase + ((cg0 + cl) << 12);
                    float v = g.x * __ldg(xc + q.x) + g.y * __ldg(xc + q.y)
                            + g.z * __ldg(xc + q.z) + g.w * __ldg(xc + q.w);
                    xo_s[(cl * 9 + n) * 64 + px] = v;
                }
            }
        }
        __syncthreads();

        // GEMM chunk: 72 kk, 16 FFMA2/kk
#pragma unroll 4
        for (int kk = 0; kk < 72; kk++) {
            float4 a0 = *(const float4*)&xo_s[kk * 64 + pg * 8];
            float4 a1 = *(const float4*)&xo_s[kk * 64 + pg * 8 + 4];
            float4 w  = *(const float4*)&w_s[kk * 64 + cg * 4];
            ull a01 = ((const ull*)&a0)[0];
            ull a23 = ((const ull*)&a0)[1];
            ull a45 = ((const ull*)&a1)[0];
            ull a67 = ((const ull*)&a1)[1];
            ull w0 = dup2(w.x), w1 = dup2(w.y), w2 = dup2(w.z), w3 = dup2(w.w);
            ffma2(acc[0][0], w0, a01); ffma2(acc[0][1], w0, a23);
            ffma2(acc[0][2], w0, a45); ffma2(acc[0][3], w0, a67);
            ffma2(acc[1][0], w1, a01); ffma2(acc[1][1], w1, a23);
            ffma2(acc[1][2], w1, a45); ffma2(acc[1][3], w1, a67);
            ffma2(acc[2][0], w2, a01); ffma2(acc[2][1], w2, a23);
            ffma2(acc[2][2], w2, a45); ffma2(acc[2][3], w2, a67);
            ffma2(acc[3][0], w3, a01); ffma2(acc[3][1], w3, a23);
            ffma2(acc[3][2], w3, a45); ffma2(acc[3][3], w3, a67);
        }
    }

    // ---- Epilogue ----------------------------------------------------------
#pragma unroll
    for (int c = 0; c < 4; c++) {
        int co = cg * 4 + c;
        float* ob = &out[(((size_t)b * C_ + co) * H_ + h) * W_ + pg * 8];
        float2 p0 = unpack2(acc[c][0]);
        float2 p1 = unpack2(acc[c][1]);
        float2 p2 = unpack2(acc[c][2]);
        float2 p3 = unpack2(acc[c][3]);
        *(float4*)ob       = make_float4(p0.x, p0.y, p1.x, p1.y);
        *(float4*)(ob + 4) = make_float4(p2.x, p2.y, p3.x, p3.y);
    }
}

// ---------------------------------------------------------------------------
extern "C" void kernel_launch(void* const* d_in, const int* in_sizes, int n_in,
                              void* d_out, int out_size) {
    const float* x     = (const float*)d_in[0];
    const float* Woff  = (const float*)d_in[1];
    const float* boff  = (const float*)d_in[2];
    const float* Wconv = (const float*)d_in[3];
    float* out = (float*)d_out;

    cudaFuncSetAttribute(k1_offset_conv,
                         cudaFuncAttributeMaxDynamicSharedMemorySize, K1_SMEM);
    cudaFuncSetAttribute(k2_sample_gemm,
                         cudaFuncAttributeMaxDynamicSharedMemorySize, K2_SMEM);

    k1_offset_conv<<<dim3(4, 8, 9), 128, K1_SMEM>>>(x, Woff, boff, Wconv);
    k2_sample_gemm<<<dim3(H_, B_), 128, K2_SMEM>>>(x, out);
}

// round 10
// speedup vs baseline: 1.0028x; 1.0028x over previous
#include <cuda_runtime.h>
#include <cstdint>

#define B_  8
#define C_  64
#define H_  64
#define W_  64
#define NN  9
#define M_  18
#define HP  66
#define KTOT 576

typedef unsigned long long ull;

__device__ float g_offset[B_ * M_ * H_ * W_];
__device__ float g_Wp[KTOT * C_];   // g_Wp[(ci*9+n)*64 + co] = Wc[co][ci*9+n]

// ---------------- helpers ----------------
__device__ __forceinline__ void ffma2(ull& d, ull a, ull b) {
    asm("fma.rn.f32x2 %0, %1, %2, %0;" : "+l"(d) : "l"(a), "l"(b));
}
__device__ __forceinline__ float2 unpack2(ull v) {
    float2 r; asm("mov.b64 {%0, %1}, %2;" : "=f"(r.x), "=f"(r.y) : "l"(v)); return r;
}
__device__ __forceinline__ ull dup2(float v) {
    ull r; asm("mov.b64 %0, {%1, %1};" : "=l"(r) : "f"(v)); return r;
}
__device__ __forceinline__ ull pack2(float lo, float hi) {
    ull r; asm("mov.b64 %0, {%1, %2};" : "=l"(r) : "f"(lo), "f"(hi)); return r;
}

// ---------------------------------------------------------------------------
// K1: offset conv (FFMA2 over m-pairs), smem-staged weights (R8-proven form).
// z==8 slice preps g_Wp.
// ---------------------------------------------------------------------------
#define K1_SMEM ((64*324 + 64*9*10*2) * 4)   // 129024 B

__global__ __launch_bounds__(256, 1)
void k1_offset_conv(const float* __restrict__ x,
                    const float* __restrict__ Woff,
                    const float* __restrict__ boff,
                    const float* __restrict__ Wc) {
    if (blockIdx.z == 8) {
        int base = (blockIdx.y * 4 + blockIdx.x) * 256 + threadIdx.x;
        for (int i = base; i < KTOT * C_; i += 16 * 256)
            g_Wp[i] = Wc[(i & 63) * KTOT + (i >> 6)];
        return;
    }

    extern __shared__ float smem[];
    float*  xs  = smem;                        // [ci][18][18]
    float2* ws2 = (float2*)(smem + 64 * 324);  // [ci][9][10]

    const int tid = threadIdx.x;
    const int b   = blockIdx.z;
    const int th0 = blockIdx.y * 16;
    const int tw0 = blockIdx.x * 16;

    const float* xb = x + (size_t)b * C_ * H_ * W_;
    for (int idx = tid; idx < 64 * 324; idx += 256) {
        int ci = idx / 324;
        int rem = idx % 324;
        int r = rem / 18, c = rem % 18;
        int gh = th0 + r - 1, gw = tw0 + c - 1;
        float v = 0.f;
        if ((unsigned)gh < H_ && (unsigned)gw < W_)
            v = xb[(ci * H_ + gh) * W_ + gw];
        xs[idx] = v;
    }
    for (int idx = tid; idx < 64 * 81; idx += 256) {
        int ci = idx / 81;
        int rem = idx % 81;
        int j = rem / 9, t = rem % 9;
        ws2[(ci * 9 + j) * 10 + t] =
            make_float2(Woff[(2 * j)     * 576 + ci * 9 + t],
                        Woff[(2 * j + 1) * 576 + ci * 9 + t]);
    }
    __syncthreads();

    const int lh = tid >> 4, lw = tid & 15;
    ull acc[9];
#pragma unroll
    for (int j = 0; j < 9; j++) acc[j] = pack2(boff[2 * j], boff[2 * j + 1]);

    for (int ci = 0; ci < 64; ci++) {
        ull xd[9];
        const float* xc = xs + ci * 324 + lh * 18 + lw;
#pragma unroll
        for (int u = 0; u < 3; u++)
#pragma unroll
            for (int v = 0; v < 3; v++)
                xd[u * 3 + v] = dup2(xc[u * 18 + v]);
#pragma unroll
        for (int j = 0; j < 9; j++) {
            const ulonglong2* wp = (const ulonglong2*)(ws2 + (ci * 9 + j) * 10);
            ulonglong2 wA = wp[0];
            ulonglong2 wB = wp[1];
            ulonglong2 wC = wp[2];
            ulonglong2 wD = wp[3];
            ull        wE = *(const ull*)(ws2 + (ci * 9 + j) * 10 + 8);
            ffma2(acc[j], wA.x, xd[0]); ffma2(acc[j], wA.y, xd[1]);
            ffma2(acc[j], wB.x, xd[2]); ffma2(acc[j], wB.y, xd[3]);
            ffma2(acc[j], wC.x, xd[4]); ffma2(acc[j], wC.y, xd[5]);
            ffma2(acc[j], wD.x, xd[6]); ffma2(acc[j], wD.y, xd[7]);
            ffma2(acc[j], wE,   xd[8]);
        }
    }

    const int h = th0 + lh, w = tw0 + lw;
#pragma unroll
    for (int j = 0; j < 9; j++) {
        float2 v = unpack2(acc[j]);
        g_offset[((b * M_ + 2 * j)     * H_ + h) * W_ + w] = v.x;
        g_offset[((b * M_ + 2 * j + 1) * H_ + h) * W_ + w] = v.y;
    }
}

// ---------------------------------------------------------------------------
// K2: window-staged bilinear sampling + GEMM.
// Block = (b, 1 row) = 64 px, 128 threads. Chunk = 4 ci x 9 n = 36 k-rows.
// smem 47.6KB -> 4 blocks/SM (16 warps). Gather via LDS from coalesced-staged
// 15-row windows; exact LDG fallback on (rare) out-of-window flag.
// ---------------------------------------------------------------------------
#define NSAMP 576
#define CKR   36
#define WINR  15
#define WELE  (WINR * 64)                        // 960
#define SM_Q    0                                // ushort4[576] = 4608
#define SM_G    (SM_Q + NSAMP * 8)               // float4[576]  = 9216
#define SM_FLAG (SM_G + NSAMP * 16)              // 16
#define SM_WS   (SM_FLAG + 16)                   // [4][960]     = 15360
#define SM_XO   (SM_WS + 4 * WELE * 4)           // [36][64]     = 9216
#define SM_W    (SM_XO + CKR * 64 * 4)           // [36][64]     = 9216
#define K2_SMEM (SM_W + CKR * 64 * 4)            // 47632

__global__ __launch_bounds__(128, 4)
void k2_sample_gemm(const float* __restrict__ x, float* __restrict__ out) {
    extern __shared__ char smc[];
    ushort4* s_q  = (ushort4*)(smc + SM_Q);
    float4*  s_g  = (float4*)(smc + SM_G);
    int*     s_fl = (int*)(smc + SM_FLAG);
    float*   ws_s = (float*)(smc + SM_WS);
    float*   xo_s = (float*)(smc + SM_XO);
    float*   w_s  = (float*)(smc + SM_W);

    const int tid = threadIdx.x;
    const int h   = blockIdx.x;
    const int b   = blockIdx.y;

    if (tid == 0) *s_fl = 0;
    __syncthreads();

    // ---- Phase A: element offsets + pre-zeroed weights + OOW flag ----------
    for (int t = tid; t < NSAMP; t += 128) {
        int n  = t >> 6;
        int px = t & 63;
        float offx = g_offset[((b * M_ + n)     * H_ + h) * W_ + px];
        float offy = g_offset[((b * M_ + 9 + n) * H_ + h) * W_ + px];
        float pX = (float)(h + 1)  + (float)(n / 3 - 1) + offx;
        float pY = (float)(px + 1) + (float)(n % 3 - 1) + offy;
        float fx = floorf(pX), fy = floorf(pY);
        int x0 = min(max((int)fx,     0), HP - 1);
        int x1 = min(max((int)fx + 1, 0), HP - 1);
        int y0 = min(max((int)fy,     0), HP - 1);
        int y1 = min(max((int)fy + 1, 0), HP - 1);
        float pxc = fminf(fmaxf(pX, 0.f), (float)(HP - 1));
        float pyc = fminf(fmaxf(pY, 0.f), (float)(HP - 1));
        float gx0 = 1.f + ((float)x0 - pxc);
        float gx1 = 1.f - ((float)x1 - pxc);
        float gy0 = 1.f + ((float)y0 - pyc);
        float gy1 = 1.f - ((float)y1 - pyc);
        int ix0 = x0 - 1, iy0 = y0 - 1, ix1 = x1 - 1, iy1 = y1 - 1;
        bool vx0 = (unsigned)ix0 < H_, vy0 = (unsigned)iy0 < W_;
        bool vx1 = (unsigned)ix1 < H_, vy1 = (unsigned)iy1 < W_;
        int cx0 = min(max(ix0, 0), H_ - 1);
        int cx1 = min(max(ix1, 0), H_ - 1);
        int cy0 = min(max(iy0, 0), W_ - 1);
        int cy1 = min(max(iy1, 0), W_ - 1);
        s_q[t] = make_ushort4((unsigned short)((cx0 << 6) + cy0),
                              (unsigned short)((cx1 << 6) + cy1),
                              (unsigned short)((cx0 << 6) + cy1),
                              (unsigned short)((cx1 << 6) + cy0));
        s_g[t] = make_float4(vx0 && vy0 ? gx0 * gy0 : 0.f,
                             vx1 && vy1 ? gx1 * gy1 : 0.f,
                             vx0 && vy1 ? gx0 * gy1 : 0.f,
                             vx1 && vy0 ? gx1 * gy0 : 0.f);
        bool oow = (vx0 && (ix0 < h - 7 || ix0 > h + 7))
                || (vx1 && (ix1 < h - 7 || ix1 > h + 7));
        if (oow) atomicOr(s_fl, 1);
    }
    __syncthreads();
    const int flag = *s_fl;

    const int px   = tid & 63;        // gather pixel
    const int half = tid >> 6;        // gather: 2-ci half
    const int ciw  = tid >> 5;        // window: ci 0..3
    const int wln  = tid & 31;        // window: lane in ci group
    const int pg   = tid >> 4;        // GEMM: 8 groups x 8 px
    const int cg   = tid & 15;        // GEMM: 16 groups x 4 co
    const float* xbase = x + (size_t)b * C_ * H_ * W_;
    const int rbase = (h - 7) * 64;

    ull acc[4][4];
#pragma unroll
    for (int i = 0; i < 4; i++)
#pragma unroll
        for (int j = 0; j < 4; j++) acc[i][j] = 0ull;

    for (int c = 0; c < 16; c++) {
        const int cg0 = c * 4;
        __syncthreads();   // prev GEMM done reading xo/w; prev gather done with ws

        // window staging: 4 ci x 15 rows x 64 cols, coalesced LDG.128
        {
            const float* xsrc = xbase + ((cg0 + ciw) << 12);
            float4* wdst = (float4*)(ws_s + ciw * WELE);
            int rowoff = wln >> 4;
            int f4     = wln & 15;
#pragma unroll
            for (int wr2 = 0; wr2 < 8; wr2++) {
                int wr = wr2 * 2 + rowoff;
                if (wr < WINR) {
                    int sr = min(max(h - 7 + wr, 0), H_ - 1);
                    wdst[wr * 16 + f4] = __ldg((const float4*)(xsrc + (sr << 6)) + f4);
                }
            }
        }
        // B chunk: 36 x 64 floats
        {
            const float4* src = (const float4*)(g_Wp + c * (CKR * 64));
            float4* dst = (float4*)w_s;
            for (int j = tid; j < CKR * 16; j += 128)
                dst[j] = src[j];
        }
        __syncthreads();

        // gather: 18 samples/thread (2 ci x 9 n)
        if (!flag) {
#pragma unroll 1
            for (int n = 0; n < NN; n++) {
                ushort4 q = s_q[n * 64 + px];
                float4  g = s_g[n * 64 + px];
                int r0 = min(max((int)q.x - rbase, 0), WELE - 1);
                int r1 = min(max((int)q.y - rbase, 0), WELE - 1);
                int r2 = min(max((int)q.z - rbase, 0), WELE - 1);
                int r3 = min(max((int)q.w - rbase, 0), WELE - 1);
#pragma unroll
                for (int c2 = 0; c2 < 2; c2++) {
                    int cl = half * 2 + c2;
                    const float* w = ws_s + cl * WELE;
                    xo_s[(cl * 9 + n) * 64 + px] =
                        g.x * w[r0] + g.y * w[r1] + g.z * w[r2] + g.w * w[r3];
                }
            }
        } else {
#pragma unroll 1
            for (int n = 0; n < NN; n++) {
                ushort4 q = s_q[n * 64 + px];
                float4  g = s_g[n * 64 + px];
#pragma unroll
                for (int c2 = 0; c2 < 2; c2++) {
                    int cl = half * 2 + c2;
                    const float* xc = xbase + ((cg0 + cl) << 12);
                    xo_s[(cl * 9 + n) * 64 + px] =
                          g.x * __ldg(xc + q.x) + g.y * __ldg(xc + q.y)
                        + g.z * __ldg(xc + q.z) + g.w * __ldg(xc + q.w);
                }
            }
        }
        __syncthreads();

        // GEMM chunk: 36 kk, 16 FFMA2/kk
#pragma unroll 4
        for (int kk = 0; kk < CKR; kk++) {
            float4 a0 = *(const float4*)&xo_s[kk * 64 + pg * 8];
            float4 a1 = *(const float4*)&xo_s[kk * 64 + pg * 8 + 4];
            float4 w  = *(const float4*)&w_s[kk * 64 + cg * 4];
            ull a01 = ((const ull*)&a0)[0];
            ull a23 = ((const ull*)&a0)[1];
            ull a45 = ((const ull*)&a1)[0];
            ull a67 = ((const ull*)&a1)[1];
            ull w0 = dup2(w.x), w1 = dup2(w.y), w2 = dup2(w.z), w3 = dup2(w.w);
            ffma2(acc[0][0], w0, a01); ffma2(acc[0][1], w0, a23);
            ffma2(acc[0][2], w0, a45); ffma2(acc[0][3], w0, a67);
            ffma2(acc[1][0], w1, a01); ffma2(acc[1][1], w1, a23);
            ffma2(acc[1][2], w1, a45); ffma2(acc[1][3], w1, a67);
            ffma2(acc[2][0], w2, a01); ffma2(acc[2][1], w2, a23);
            ffma2(acc[2][2], w2, a45); ffma2(acc[2][3], w2, a67);
            ffma2(acc[3][0], w3, a01); ffma2(acc[3][1], w3, a23);
            ffma2(acc[3][2], w3, a45); ffma2(acc[3][3], w3, a67);
        }
    }

    // ---- Epilogue ----------------------------------------------------------
#pragma unroll
    for (int c = 0; c < 4; c++) {
        int co = cg * 4 + c;
        float* ob = &out[(((size_t)b * C_ + co) * H_ + h) * W_ + pg * 8];
        float2 p0 = unpack2(acc[c][0]);
        float2 p1 = unpack2(acc[c][1]);
        float2 p2 = unpack2(acc[c][2]);
        float2 p3 = unpack2(acc[c][3]);
        *(float4*)ob       = make_float4(p0.x, p0.y, p1.x, p1.y);
        *(float4*)(ob + 4) = make_float4(p2.x, p2.y, p3.x, p3.y);
    }
}

// ---------------------------------------------------------------------------
extern "C" void kernel_launch(void* const* d_in, const int* in_sizes, int n_in,
                              void* d_out, int out_size) {
    const float* x     = (const float*)d_in[0];
    const float* Woff  = (const float*)d_in[1];
    const float* boff  = (const float*)d_in[2];
    const float* Wconv = (const float*)d_in[3];
    float* out = (float*)d_out;

    cudaFuncSetAttribute(k1_offset_conv,
                         cudaFuncAttributeMaxDynamicSharedMemorySize, K1_SMEM);
    cudaFuncSetAttribute(k2_sample_gemm,
                         cudaFuncAttributeMaxDynamicSharedMemorySize, K2_SMEM);

    k1_offset_conv<<<dim3(4, 4, 9), 256, K1_SMEM>>>(x, Woff, boff, Wconv);
    k2_sample_gemm<<<dim3(H_, B_), 128, K2_SMEM>>>(x, out);
}

// round 11
// speedup vs baseline: 1.0870x; 1.0839x over previous
#include <cuda_runtime.h>
#include <cstdint>

#define B_  8
#define C_  64
#define H_  64
#define W_  64
#define NN  9
#define M_  18
#define HP  66
#define KTOT 576

typedef unsigned long long ull;

__device__ float g_off2[2][B_ * M_ * H_ * W_];   // split-k partial offsets
__device__ float g_Wp[KTOT * C_];                // [(n*64+ci)*64 + co]

// ---------------- helpers ----------------
__device__ __forceinline__ void ffma2(ull& d, ull a, ull b) {
    asm("fma.rn.f32x2 %0, %1, %2, %0;" : "+l"(d) : "l"(a), "l"(b));
}
__device__ __forceinline__ float2 unpack2(ull v) {
    float2 r; asm("mov.b64 {%0, %1}, %2;" : "=f"(r.x), "=f"(r.y) : "l"(v)); return r;
}
__device__ __forceinline__ ull dup2(float v) {
    ull r; asm("mov.b64 %0, {%1, %1};" : "=l"(r) : "f"(v)); return r;
}
__device__ __forceinline__ ull pack2(float lo, float hi) {
    ull r; asm("mov.b64 %0, {%1, %2};" : "=l"(r) : "f"(lo), "f"(hi)); return r;
}

// ---------------------------------------------------------------------------
// K1: offset conv, split-k over ci (2 blocks x 32 ci per 16x16 tile).
// blockIdx.z = b*2 + half; z==16 slice preps g_Wp.
// ---------------------------------------------------------------------------
#define CI_HALF 32
#define K1_SMEM ((CI_HALF*324 + CI_HALF*9*10*2) * 4)   // 64512 B

__global__ __launch_bounds__(256, 3)
void k1_offset_conv(const float* __restrict__ x,
                    const float* __restrict__ Woff,
                    const float* __restrict__ boff,
                    const float* __restrict__ Wc) {
    if (blockIdx.z == 16) {
        int base = (blockIdx.y * 4 + blockIdx.x) * 256 + threadIdx.x;
        for (int i = base; i < KTOT * C_; i += 16 * 256) {
            int kp = i >> 6;
            int co = i & 63;
            int n  = kp >> 6;
            int ci = kp & 63;
            g_Wp[i] = Wc[co * KTOT + ci * 9 + n];
        }
        return;
    }

    extern __shared__ float smem[];
    float*  xs  = smem;                             // [cil][18][18]
    float2* ws2 = (float2*)(smem + CI_HALF * 324);  // [cil][9][10]

    const int tid = threadIdx.x;
    const int b   = blockIdx.z >> 1;
    const int hf  = blockIdx.z & 1;
    const int ci0 = hf * CI_HALF;
    const int th0 = blockIdx.y * 16;
    const int tw0 = blockIdx.x * 16;

    const float* xb = x + (size_t)b * C_ * H_ * W_;
    for (int idx = tid; idx < CI_HALF * 324; idx += 256) {
        int cil = idx / 324;
        int rem = idx % 324;
        int r = rem / 18, c = rem % 18;
        int gh = th0 + r - 1, gw = tw0 + c - 1;
        float v = 0.f;
        if ((unsigned)gh < H_ && (unsigned)gw < W_)
            v = xb[((ci0 + cil) * H_ + gh) * W_ + gw];
        xs[idx] = v;
    }
    for (int idx = tid; idx < CI_HALF * 81; idx += 256) {
        int cil = idx / 81;
        int rem = idx % 81;
        int j = rem / 9, t = rem % 9;
        int ci = ci0 + cil;
        ws2[(cil * 9 + j) * 10 + t] =
            make_float2(Woff[(2 * j)     * 576 + ci * 9 + t],
                        Woff[(2 * j + 1) * 576 + ci * 9 + t]);
    }
    __syncthreads();

    const int lh = tid >> 4, lw = tid & 15;
    ull acc[9];
#pragma unroll
    for (int j = 0; j < 9; j++)
        acc[j] = hf ? 0ull : pack2(boff[2 * j], boff[2 * j + 1]);

    for (int cil = 0; cil < CI_HALF; cil++) {
        ull xd[9];
        const float* xc = xs + cil * 324 + lh * 18 + lw;
#pragma unroll
        for (int u = 0; u < 3; u++)
#pragma unroll
            for (int v = 0; v < 3; v++)
                xd[u * 3 + v] = dup2(xc[u * 18 + v]);
#pragma unroll
        for (int j = 0; j < 9; j++) {
            const ulonglong2* wp = (const ulonglong2*)(ws2 + (cil * 9 + j) * 10);
            ulonglong2 wA = wp[0];
            ulonglong2 wB = wp[1];
            ulonglong2 wC = wp[2];
            ulonglong2 wD = wp[3];
            ull        wE = *(const ull*)(ws2 + (cil * 9 + j) * 10 + 8);
            ffma2(acc[j], wA.x, xd[0]); ffma2(acc[j], wA.y, xd[1]);
            ffma2(acc[j], wB.x, xd[2]); ffma2(acc[j], wB.y, xd[3]);
            ffma2(acc[j], wC.x, xd[4]); ffma2(acc[j], wC.y, xd[5]);
            ffma2(acc[j], wD.x, xd[6]); ffma2(acc[j], wD.y, xd[7]);
            ffma2(acc[j], wE,   xd[8]);
        }
    }

    const int h = th0 + lh, w = tw0 + lw;
    float* dst = g_off2[hf];
#pragma unroll
    for (int j = 0; j < 9; j++) {
        float2 v = unpack2(acc[j]);
        dst[((b * M_ + 2 * j)     * H_ + h) * W_ + w] = v.x;
        dst[((b * M_ + 2 * j + 1) * H_ + h) * W_ + w] = v.y;
    }
}

// ---------------------------------------------------------------------------
// K2: fused bilinear sampling + GEMM (R8-proven form).
// Block = (b, 1 row) = 64 px, 128 thr. Thread tile 8px x 4co; warp 2pg x 16cg.
// 18 chunks of 32 k-rows (permuted k = n*64+ci). smem 29.5KB.
// ---------------------------------------------------------------------------
#define NSAMP 576
#define CK    32
#define SM_Q  0                                  // ushort4[576] = 4608
#define SM_G  (SM_Q + NSAMP * 8)                 // float4[576]  = 9216
#define SM_XO (SM_G + NSAMP * 16)                // [32][64] = 8192
#define SM_W  (SM_XO + CK * 64 * 4)              // [32][64] = 8192
#define K2_SMEM (SM_W + CK * 64 * 4)             // 30208

__global__ __launch_bounds__(128, 5)
void k2_sample_gemm(const float* __restrict__ x, float* __restrict__ out) {
    extern __shared__ char smc[];
    ushort4* s_q  = (ushort4*)(smc + SM_Q);
    float4*  s_g  = (float4*)(smc + SM_G);
    float*   xo_s = (float*)(smc + SM_XO);
    float*   w_s  = (float*)(smc + SM_W);

    const int tid = threadIdx.x;
    const int h   = blockIdx.x;
    const int b   = blockIdx.y;

    // ---- Phase A: 4 clamped element-offsets + pre-zeroed weights -----------
    for (int t = tid; t < NSAMP; t += 128) {
        int n  = t >> 6;
        int px = t & 63;
        int ix = ((b * M_ + n)     * H_ + h) * W_ + px;
        int iy = ((b * M_ + 9 + n) * H_ + h) * W_ + px;
        float offx = g_off2[0][ix] + g_off2[1][ix];
        float offy = g_off2[0][iy] + g_off2[1][iy];
        float pX = (float)(h + 1)  + (float)(n / 3 - 1) + offx;
        float pY = (float)(px + 1) + (float)(n % 3 - 1) + offy;
        float fx = floorf(pX), fy = floorf(pY);
        int x0 = min(max((int)fx,     0), HP - 1);
        int x1 = min(max((int)fx + 1, 0), HP - 1);
        int y0 = min(max((int)fy,     0), HP - 1);
        int y1 = min(max((int)fy + 1, 0), HP - 1);
        float pxc = fminf(fmaxf(pX, 0.f), (float)(HP - 1));
        float pyc = fminf(fmaxf(pY, 0.f), (float)(HP - 1));
        float gx0 = 1.f + ((float)x0 - pxc);
        float gx1 = 1.f - ((float)x1 - pxc);
        float gy0 = 1.f + ((float)y0 - pyc);
        float gy1 = 1.f - ((float)y1 - pyc);
        int ix0 = x0 - 1, iy0 = y0 - 1, ix1 = x1 - 1, iy1 = y1 - 1;
        bool vx0 = (unsigned)ix0 < H_, vy0 = (unsigned)iy0 < W_;
        bool vx1 = (unsigned)ix1 < H_, vy1 = (unsigned)iy1 < W_;
        int cx0 = min(max(ix0, 0), H_ - 1);
        int cx1 = min(max(ix1, 0), H_ - 1);
        int cy0 = min(max(iy0, 0), W_ - 1);
        int cy1 = min(max(iy1, 0), W_ - 1);
        s_q[t] = make_ushort4((unsigned short)((cx0 << 6) + cy0),
                              (unsigned short)((cx1 << 6) + cy1),
                              (unsigned short)((cx0 << 6) + cy1),
                              (unsigned short)((cx1 << 6) + cy0));
        s_g[t] = make_float4(vx0 && vy0 ? gx0 * gy0 : 0.f,
                             vx1 && vy1 ? gx1 * gy1 : 0.f,
                             vx0 && vy1 ? gx0 * gy1 : 0.f,
                             vx1 && vy0 ? gx1 * gy0 : 0.f);
    }

    const int px   = tid & 63;
    const int half = tid >> 6;
    const int pg   = tid >> 4;
    const int cg   = tid & 15;
    const float* xbase = x + (size_t)b * C_ * H_ * W_;

    ull acc[4][4];
#pragma unroll
    for (int i = 0; i < 4; i++)
#pragma unroll
        for (int j = 0; j < 4; j++) acc[i][j] = 0ull;

    for (int c = 0; c < 18; c++) {
        const int n   = c >> 1;
        const int ci0 = (c & 1) * 32;
        __syncthreads();

        // B chunk
        {
            const float4* src = (const float4*)(g_Wp + c * (CK * 64));
            float4* dst = (float4*)w_s;
#pragma unroll
            for (int j = 0; j < 4; j++)
                dst[j * 128 + tid] = src[j * 128 + tid];
        }

        // gather: meta once, 16 ci per thread
        {
            ushort4 q = s_q[n * 64 + px];
            float4  g = s_g[n * 64 + px];
#pragma unroll 4
            for (int i = 0; i < 16; i++) {
                int lk = half * 16 + i;
                int ci = ci0 + lk;
                const float* xc = xbase + (ci << 12);
                float v = g.x * __ldg(xc + q.x) + g.y * __ldg(xc + q.y)
                        + g.z * __ldg(xc + q.z) + g.w * __ldg(xc + q.w);
                xo_s[lk * 64 + px] = v;
            }
        }
        __syncthreads();

        // GEMM chunk: 32 kk, 16 FFMA2/kk
#pragma unroll 4
        for (int kk = 0; kk < CK; kk++) {
            float4 a0 = *(const float4*)&xo_s[kk * 64 + pg * 8];
            float4 a1 = *(const float4*)&xo_s[kk * 64 + pg * 8 + 4];
            float4 w  = *(const float4*)&w_s[kk * 64 + cg * 4];
            ull a01 = ((const ull*)&a0)[0];
            ull a23 = ((const ull*)&a0)[1];
            ull a45 = ((const ull*)&a1)[0];
            ull a67 = ((const ull*)&a1)[1];
            ull w0 = dup2(w.x), w1 = dup2(w.y), w2 = dup2(w.z), w3 = dup2(w.w);
            ffma2(acc[0][0], w0, a01); ffma2(acc[0][1], w0, a23);
            ffma2(acc[0][2], w0, a45); ffma2(acc[0][3], w0, a67);
            ffma2(acc[1][0], w1, a01); ffma2(acc[1][1], w1, a23);
            ffma2(acc[1][2], w1, a45); ffma2(acc[1][3], w1, a67);
            ffma2(acc[2][0], w2, a01); ffma2(acc[2][1], w2, a23);
            ffma2(acc[2][2], w2, a45); ffma2(acc[2][3], w2, a67);
            ffma2(acc[3][0], w3, a01); ffma2(acc[3][1], w3, a23);
            ffma2(acc[3][2], w3, a45); ffma2(acc[3][3], w3, a67);
        }
    }

    // ---- Epilogue ----------------------------------------------------------
#pragma unroll
    for (int c = 0; c < 4; c++) {
        int co = cg * 4 + c;
        float* ob = &out[(((size_t)b * C_ + co) * H_ + h) * W_ + pg * 8];
        float2 p0 = unpack2(acc[c][0]);
        float2 p1 = unpack2(acc[c][1]);
        float2 p2 = unpack2(acc[c][2]);
        float2 p3 = unpack2(acc[c][3]);
        *(float4*)ob       = make_float4(p0.x, p0.y, p1.x, p1.y);
        *(float4*)(ob + 4) = make_float4(p2.x, p2.y, p3.x, p3.y);
    }
}

// ---------------------------------------------------------------------------
extern "C" void kernel_launch(void* const* d_in, const int* in_sizes, int n_in,
                              void* d_out, int out_size) {
    const float* x     = (const float*)d_in[0];
    const float* Woff  = (const float*)d_in[1];
    const float* boff  = (const float*)d_in[2];
    const float* Wconv = (const float*)d_in[3];
    float* out = (float*)d_out;

    cudaFuncSetAttribute(k1_offset_conv,
                         cudaFuncAttributeMaxDynamicSharedMemorySize, K1_SMEM);
    cudaFuncSetAttribute(k2_sample_gemm,
                         cudaFuncAttributeMaxDynamicSharedMemorySize, K2_SMEM);

    k1_offset_conv<<<dim3(4, 4, 17), 256, K1_SMEM>>>(x, Woff, boff, Wconv);
    k2_sample_gemm<<<dim3(H_, B_), 128, K2_SMEM>>>(x, out);
}